// round 11
// baseline (speedup 1.0000x reference)
#include <cuda_runtime.h>
#include <cuda_bf16.h>

#define Bn 8
#define Sn 2048
#define Dn 256
#define Hn 4
#define DHn 64

// ---------------- scratch (static device arrays; no allocation) ----------------
__device__ float g_qs[Bn*Hn*Sn*DHn];     // 16 MB  [B,H,S,DH]  tf32-pre-rounded
__device__ float g_ks[Bn*Hn*Sn*DHn];     // 16 MB  [B,H,S,DH]  tf32-pre-rounded
__device__ float g_vs[Bn*Sn*DHn];        //  4 MB  [B,S,DH]    tf32-pre-rounded
__device__ float g_heads[Bn*Hn*Sn*DHn];  // 16 MB  [B,H,S,DH]  (carries 1/(4*rowsum))
__device__ float g_rowsum[Bn*Hn*Sn];     // 256 KB
__device__ unsigned g_mbits[Bn*Sn*(Sn/32)]; // 16.8 MB bit-packed mask

// ---------------- helpers ----------------
__device__ __forceinline__ unsigned f2tf(float x) {
    unsigned u;
    asm("cvt.rna.tf32.f32 %0, %1;" : "=r"(u) : "f"(x));
    return u;
}
__device__ __forceinline__ float tf32r(float x) { return __uint_as_float(f2tf(x)); }
__device__ __forceinline__ void mma8(float* c, const unsigned* a, const unsigned* b) {
    asm volatile("mma.sync.aligned.m16n8k8.row.col.f32.tf32.tf32.f32 "
        "{%0,%1,%2,%3}, {%4,%5,%6,%7}, {%8,%9}, {%0,%1,%2,%3};\n"
        : "+f"(c[0]), "+f"(c[1]), "+f"(c[2]), "+f"(c[3])
        : "r"(a[0]), "r"(a[1]), "r"(a[2]), "r"(a[3]), "r"(b[0]), "r"(b[1]));
}
__device__ __forceinline__ void mma16(float* c, const unsigned* a, const unsigned* b) {
    asm volatile("mma.sync.aligned.m16n8k16.row.col.f32.bf16.bf16.f32 "
        "{%0,%1,%2,%3}, {%4,%5,%6,%7}, {%8,%9}, {%0,%1,%2,%3};\n"
        : "+f"(c[0]), "+f"(c[1]), "+f"(c[2]), "+f"(c[3])
        : "r"(a[0]), "r"(a[1]), "r"(a[2]), "r"(a[3]), "r"(b[0]), "r"(b[1]));
}
__device__ __forceinline__ void bsplit(float x, __nv_bfloat16 &hi, __nv_bfloat16 &lo) {
    hi = __float2bfloat16_rn(x);
    lo = __float2bfloat16_rn(x - __bfloat162float(hi));
}

// FMA-pipe exp(s/8): magic-constant round + degree-5 poly + exponent splice. rel err ~2e-6.
__device__ __forceinline__ float fexp8(float s) {
    const float c = 0.18033688011112042f;   // log2(e)/8
    const float MAGIC = 12582912.0f;        // 1.5 * 2^23
    float t = fmaf(s, c, MAGIC);
    float k = t - MAGIC;
    float f = fmaf(s, c, -k);               // f in [-0.5, 0.5]
    float p = 1.3333558146e-3f;
    p = fmaf(p, f, 9.6181291076e-3f);
    p = fmaf(p, f, 5.5504108665e-2f);
    p = fmaf(p, f, 2.4022650696e-1f);
    p = fmaf(p, f, 6.9314718056e-1f);
    p = fmaf(p, f, 1.0f);
    int ik = __float_as_int(t) << 23;
    return __int_as_float(__float_as_int(p) + ik);
}

#define CP_ASYNC16(dst_u32, src) \
    asm volatile("cp.async.cg.shared.global [%0], [%1], 16;" :: "r"(dst_u32), "l"(src))
#define CP_ASYNC8(dst_u32, src) \
    asm volatile("cp.async.ca.shared.global [%0], [%1], 8;" :: "r"(dst_u32), "l"(src))
#define CP_COMMIT() asm volatile("cp.async.commit_group;" ::: "memory")

// ================= Kernel 0: bit-pack the mask =================
__global__ void pack_mask_kernel(const int* __restrict__ mask) {
    size_t i = (size_t)blockIdx.x * 256 + threadIdx.x;
    int m = mask[i] != 0;
    unsigned bal = __ballot_sync(0xffffffffu, m);
    if ((threadIdx.x & 31) == 0) g_mbits[i >> 5] = bal;
}

// ================= Kernel 1: projections via bf16x3 GEMM, tf32-rounded outputs ====
__global__ __launch_bounds__(256) void proj_kernel(
    const float* __restrict__ q, const float* __restrict__ k, const float* __restrict__ v,
    const float* __restrict__ Wq, const float* __restrict__ Wk, const float* __restrict__ Wv)
{
    int z = blockIdx.z;
    if (z == 2 && blockIdx.x > 0) return;
    __shared__ __nv_bfloat16 Ah[128][40];
    __shared__ __nv_bfloat16 Al[128][40];
    __shared__ __nv_bfloat16 Bh[64][40];   // stored as [n][k]
    __shared__ __nv_bfloat16 Bl[64][40];

    const float* X = (z == 0) ? q : (z == 1) ? k : v;
    const float* W = (z == 0) ? (Wq + (size_t)blockIdx.x * Dn * DHn)
                   : (z == 1) ? (Wk + (size_t)blockIdx.x * Dn * DHn) : Wv;
    int M0 = blockIdx.y * 128;
    int tid = threadIdx.x;
    int warp = tid >> 5, lane = tid & 31;
    int g = lane >> 2, t = lane & 3;
    int wm0 = (warp >> 1) * 32, wn0 = (warp & 1) * 32;

    float c[2][4][4];
    #pragma unroll
    for (int mt = 0; mt < 2; mt++)
        #pragma unroll
        for (int nt = 0; nt < 4; nt++)
            #pragma unroll
            for (int i = 0; i < 4; i++) c[mt][nt][i] = 0.f;

    for (int kc = 0; kc < 8; kc++) {
        int K0 = kc * 32;
        #pragma unroll
        for (int it = 0; it < 4; it++) {
            int i = tid + it * 256;
            int r = i >> 3, c4 = (i & 7) << 2;
            float4 val = *reinterpret_cast<const float4*>(&X[(size_t)(M0 + r) * Dn + K0 + c4]);
            __nv_bfloat16 hi, lo;
            bsplit(val.x, hi, lo); Ah[r][c4]   = hi; Al[r][c4]   = lo;
            bsplit(val.y, hi, lo); Ah[r][c4+1] = hi; Al[r][c4+1] = lo;
            bsplit(val.z, hi, lo); Ah[r][c4+2] = hi; Al[r][c4+2] = lo;
            bsplit(val.w, hi, lo); Ah[r][c4+3] = hi; Al[r][c4+3] = lo;
        }
        #pragma unroll
        for (int it = 0; it < 2; it++) {
            int i = tid + it * 256;
            int r = i >> 4, c4 = (i & 15) << 2;   // r = k row (0..31), c4 = n
            float4 val = *reinterpret_cast<const float4*>(&W[(size_t)(K0 + r) * DHn + c4]);
            __nv_bfloat16 hi, lo;
            bsplit(val.x, hi, lo); Bh[c4][r]   = hi; Bl[c4][r]   = lo;
            bsplit(val.y, hi, lo); Bh[c4+1][r] = hi; Bl[c4+1][r] = lo;
            bsplit(val.z, hi, lo); Bh[c4+2][r] = hi; Bl[c4+2][r] = lo;
            bsplit(val.w, hi, lo); Bh[c4+3][r] = hi; Bl[c4+3][r] = lo;
        }
        __syncthreads();
        #pragma unroll
        for (int kk = 0; kk < 2; kk++) {
            int k0 = kk * 16;
            unsigned ah[2][4], al[2][4], bh[4][2], bl[4][2];
            #pragma unroll
            for (int mt = 0; mt < 2; mt++) {
                int rb = wm0 + mt * 16;
                ah[mt][0] = *reinterpret_cast<const unsigned*>(&Ah[rb + g][k0 + 2*t]);
                ah[mt][1] = *reinterpret_cast<const unsigned*>(&Ah[rb + 8 + g][k0 + 2*t]);
                ah[mt][2] = *reinterpret_cast<const unsigned*>(&Ah[rb + g][k0 + 8 + 2*t]);
                ah[mt][3] = *reinterpret_cast<const unsigned*>(&Ah[rb + 8 + g][k0 + 8 + 2*t]);
                al[mt][0] = *reinterpret_cast<const unsigned*>(&Al[rb + g][k0 + 2*t]);
                al[mt][1] = *reinterpret_cast<const unsigned*>(&Al[rb + 8 + g][k0 + 2*t]);
                al[mt][2] = *reinterpret_cast<const unsigned*>(&Al[rb + g][k0 + 8 + 2*t]);
                al[mt][3] = *reinterpret_cast<const unsigned*>(&Al[rb + 8 + g][k0 + 8 + 2*t]);
            }
            #pragma unroll
            for (int nt = 0; nt < 4; nt++) {
                int cb = wn0 + nt * 8 + g;
                bh[nt][0] = *reinterpret_cast<const unsigned*>(&Bh[cb][k0 + 2*t]);
                bh[nt][1] = *reinterpret_cast<const unsigned*>(&Bh[cb][k0 + 8 + 2*t]);
                bl[nt][0] = *reinterpret_cast<const unsigned*>(&Bl[cb][k0 + 2*t]);
                bl[nt][1] = *reinterpret_cast<const unsigned*>(&Bl[cb][k0 + 8 + 2*t]);
            }
            #pragma unroll
            for (int mt = 0; mt < 2; mt++)
                #pragma unroll
                for (int nt = 0; nt < 4; nt++) {
                    mma16(c[mt][nt], ah[mt], bh[nt]);
                    mma16(c[mt][nt], ah[mt], bl[nt]);
                    mma16(c[mt][nt], al[mt], bh[nt]);
                }
        }
        __syncthreads();
    }
    #pragma unroll
    for (int mt = 0; mt < 2; mt++)
        #pragma unroll
        for (int nt = 0; nt < 4; nt++) {
            int e = wn0 + nt * 8 + 2 * t;
            #pragma unroll
            for (int half = 0; half < 2; half++) {
                int r = M0 + wm0 + mt * 16 + half * 8 + g;
                int bb = r >> 11, s = r & 2047;
                float2 val = make_float2(tf32r(c[mt][nt][half * 2]), tf32r(c[mt][nt][half * 2 + 1]));
                if (z == 2) {
                    *reinterpret_cast<float2*>(&g_vs[((size_t)bb * Sn + s) * DHn + e]) = val;
                } else {
                    float* dst = (z == 0) ? g_qs : g_ks;
                    int h = blockIdx.x;
                    *reinterpret_cast<float2*>(&dst[(((size_t)(bb * Hn + h)) * Sn + s) * DHn + e]) = val;
                }
            }
        }
}

// ================= Kernel 2: fused attention (cp.async pipelined, 512 threads) ====
// 16 warps as 8x2: warp tile 16 (M) x 32 (N). smem identical to R9 (143872 B).
__global__ __launch_bounds__(512) void attn_kernel(float* __restrict__ attn_out)
{
    extern __shared__ float sm[];
    float* Qs = sm;                    // pitch 68
    float* Ks2 = sm + 8704;            // per-buf 4352, pitch 68
    float* Vs2 = sm + 17408;           // per-buf 4608, pitch 72
    float* Ps = sm + 26624;            // pitch 68
    unsigned* m2 = reinterpret_cast<unsigned*>(sm + 35328); // per-buf 256, pitch 2
    float* rowsum = sm + 35840;

    int st = blockIdx.x, h = blockIdx.y, b = blockIdx.z;
    int bh = b * Hn + h;
    int S0 = st * 128;
    int tid = threadIdx.x, warp = tid >> 5, lane = tid & 31;
    int g = lane >> 2, t = lane & 3;
    int wm0 = (warp >> 1) * 16, wn0 = (warp & 1) * 32;

    const float* qsrc = g_qs + ((size_t)bh * Sn + S0) * DHn;
    const float* ksrc = g_ks + (size_t)bh * Sn * DHn;
    const float* vsrc = g_vs + (size_t)b * Sn * DHn;
    const unsigned* msrc = g_mbits + ((size_t)b * Sn + S0) * (Sn / 32);
    float* aout = attn_out + (size_t)bh * Sn * Sn;

    unsigned smem_base = (unsigned)__cvta_generic_to_shared(sm);

    // async stage of K/V/mask for tile `tc` into buffer `buf`
    auto stage = [&](int tc, int buf) {
        int T0 = tc * 64;
        unsigned kbase = smem_base + (8704 + buf * 4352) * 4;
        unsigned vbase = smem_base + (17408 + buf * 4608) * 4;
        #pragma unroll
        for (int it = 0; it < 2; it++) {
            int ci = tid + it * 512;      // 1024 chunks of 16B for K
            int r = ci >> 4, c16 = ci & 15;
            CP_ASYNC16(kbase + (r * 68 + c16 * 4) * 4, &ksrc[(size_t)(T0 + r) * DHn + c16 * 4]);
            CP_ASYNC16(vbase + (r * 72 + c16 * 4) * 4, &vsrc[(size_t)(T0 + r) * DHn + c16 * 4]);
        }
        if (tid < 128) {
            unsigned mbase = smem_base + (35328 + buf * 256) * 4;
            CP_ASYNC8(mbase + tid * 8, &msrc[(size_t)tid * (Sn / 32) + (T0 >> 5)]);
        }
    };

    // prologue: kick off tile 0, stage Q with plain loads
    stage(0, 0);
    CP_COMMIT();
    #pragma unroll
    for (int it = 0; it < 4; it++) {
        int i = tid + it * 512;
        int r = i >> 4, c4 = (i & 15) << 2;
        float4 val = *reinterpret_cast<const float4*>(&qsrc[(size_t)r * DHn + c4]);
        *reinterpret_cast<float4*>(&Qs[r * 68 + c4]) = val;
    }
    if (tid < 128) rowsum[tid] = 0.f;

    float cO[4][4];
    #pragma unroll
    for (int nt = 0; nt < 4; nt++)
        #pragma unroll
        for (int i = 0; i < 4; i++) cO[nt][i] = 0.f;
    float rpart[2] = {0.f, 0.f};

    for (int tc = 0; tc < 32; tc++) {
        int buf = tc & 1;
        int T0 = tc * 64;
        float* Kb = Ks2 + buf * 4352;
        float* Vb = Vs2 + buf * 4608;
        unsigned* Mb = m2 + buf * 256;

        // issue next tile into the other buffer (safe: freed by last iteration's barrier)
        if (tc + 1 < 32) {
            stage(tc + 1, buf ^ 1);
            CP_COMMIT();
            asm volatile("cp.async.wait_group 1;" ::: "memory");
        } else {
            asm volatile("cp.async.wait_group 0;" ::: "memory");
        }
        __syncthreads();

        // ---- QK^T (tf32 x1) ----
        float cS[4][4];
        #pragma unroll
        for (int nt = 0; nt < 4; nt++)
            #pragma unroll
            for (int i = 0; i < 4; i++) cS[nt][i] = 0.f;
        #pragma unroll
        for (int kk = 0; kk < 8; kk++) {
            int k0 = kk * 8;
            unsigned a[4], bf[4][2];
            a[0] = __float_as_uint(Qs[(wm0 + g) * 68 + k0 + t]);
            a[1] = __float_as_uint(Qs[(wm0 + 8 + g) * 68 + k0 + t]);
            a[2] = __float_as_uint(Qs[(wm0 + g) * 68 + k0 + t + 4]);
            a[3] = __float_as_uint(Qs[(wm0 + 8 + g) * 68 + k0 + t + 4]);
            #pragma unroll
            for (int nt = 0; nt < 4; nt++) {
                int cb = wn0 + nt * 8 + g;
                bf[nt][0] = __float_as_uint(Kb[cb * 68 + k0 + t]);
                bf[nt][1] = __float_as_uint(Kb[cb * 68 + k0 + t + 4]);
            }
            #pragma unroll
            for (int nt = 0; nt < 4; nt++)
                mma8(cS[nt], a, bf[nt]);
        }

        // ---- mask + exp (FMA pipe) + write attn + stage tf32 P ----
        #pragma unroll
        for (int nt = 0; nt < 4; nt++) {
            int tloc = wn0 + nt * 8 + 2 * t;
            int tg = T0 + tloc;
            #pragma unroll
            for (int half = 0; half < 2; half++) {
                int rloc = wm0 + half * 8 + g;
                int sg = S0 + rloc;
                unsigned mw = Mb[rloc * 2 + (tloc >> 5)];
                int sh = tloc & 31;
                float e0 = fexp8(cS[nt][half * 2]);
                float e1 = fexp8(cS[nt][half * 2 + 1]);
                float p0 = ((mw >> sh) & 1u)       ? e0 : 0.f;
                float p1 = ((mw >> (sh + 1)) & 1u) ? e1 : 0.f;
                *reinterpret_cast<float2*>(&aout[(size_t)sg * Sn + tg]) = make_float2(p0, p1);
                *reinterpret_cast<float2*>(&Ps[rloc * 68 + tloc]) = make_float2(tf32r(p0), tf32r(p1));
                rpart[half] += p0 + p1;
            }
        }
        __syncthreads();

        // ---- O += P @ V (tf32; raw bit loads) ----
        #pragma unroll
        for (int kk = 0; kk < 8; kk++) {
            int k0 = kk * 8;
            unsigned a[4], bf[4][2];
            a[0] = __float_as_uint(Ps[(wm0 + g) * 68 + k0 + t]);
            a[1] = __float_as_uint(Ps[(wm0 + 8 + g) * 68 + k0 + t]);
            a[2] = __float_as_uint(Ps[(wm0 + g) * 68 + k0 + t + 4]);
            a[3] = __float_as_uint(Ps[(wm0 + 8 + g) * 68 + k0 + t + 4]);
            #pragma unroll
            for (int nt = 0; nt < 4; nt++) {
                int cb = wn0 + nt * 8 + g;
                bf[nt][0] = __float_as_uint(Vb[(k0 + t) * 72 + cb]);
                bf[nt][1] = __float_as_uint(Vb[(k0 + t + 4) * 72 + cb]);
            }
            #pragma unroll
            for (int nt = 0; nt < 4; nt++)
                mma8(cO[nt], a, bf[nt]);
        }
        __syncthreads();   // frees Kb/Vb/Mb/Ps for next iteration
    }

    // ---- rowsum reduce ----
    #pragma unroll
    for (int half = 0; half < 2; half++) {
        float v = rpart[half];
        v += __shfl_xor_sync(0xffffffffu, v, 1);
        v += __shfl_xor_sync(0xffffffffu, v, 2);
        if (t == 0) atomicAdd(&rowsum[wm0 + half * 8 + g], v);
    }
    __syncthreads();

    // ---- write heads (scaled by 0.25/rowsum) + rowsum ----
    float* hdst = g_heads + (size_t)bh * Sn * DHn;
    #pragma unroll
    for (int nt = 0; nt < 4; nt++) {
        int e = wn0 + nt * 8 + 2 * t;
        #pragma unroll
        for (int half = 0; half < 2; half++) {
            int rloc = wm0 + half * 8 + g;
            float inv = 0.25f / rowsum[rloc];
            float2 val = make_float2(cO[nt][half * 2] * inv, cO[nt][half * 2 + 1] * inv);
            *reinterpret_cast<float2*>(&hdst[(size_t)(S0 + rloc) * DHn + e]) = val;
        }
    }
    if (tid < 128) g_rowsum[(size_t)bh * Sn + S0 + tid] = rowsum[tid];
}

// ================= Kernel 3: normalize attn rows (streaming, DRAM roofline) ======
__global__ void rescale_kernel(float* __restrict__ attn) {
    int row = blockIdx.x;
    float inv = 1.f / g_rowsum[row];
    float4* p = reinterpret_cast<float4*>(attn + (size_t)row * Sn);
    int tid = threadIdx.x;
    #pragma unroll
    for (int i = 0; i < 2; i++) {
        float4 v = p[tid + i * 256];
        v.x *= inv; v.y *= inv; v.z *= inv; v.w *= inv;
        p[tid + i * 256] = v;
    }
}

// ================= Kernel 4: out = mean_h(heads) @ Wo =================
__global__ __launch_bounds__(256) void final_kernel(
    const float* __restrict__ Wo, float* __restrict__ out)
{
    __shared__ float avg[16][64];
    int r0 = blockIdx.x * 16;
    int tid = threadIdx.x;
    #pragma unroll
    for (int it = 0; it < 4; it++) {
        int i = tid + it * 256;
        int rr = i >> 6, e = i & 63;
        int R = r0 + rr;
        int bb = R >> 11, s = R & 2047;
        size_t base = ((size_t)(bb * Hn) * Sn + s) * DHn + e;
        avg[rr][e] = g_heads[base] + g_heads[base + (size_t)Sn * DHn]
                   + g_heads[base + 2 * (size_t)Sn * DHn] + g_heads[base + 3 * (size_t)Sn * DHn];
    }
    __syncthreads();
    float acc[16];
    #pragma unroll
    for (int i = 0; i < 16; i++) acc[i] = 0.f;
    int d = tid;
    #pragma unroll 16
    for (int e = 0; e < 64; e++) {
        float w = Wo[e * Dn + d];
        #pragma unroll
        for (int i = 0; i < 16; i++) acc[i] += avg[i][e] * w;
    }
    #pragma unroll
    for (int i = 0; i < 16; i++) out[(size_t)(r0 + i) * Dn + d] = acc[i];
}

// ================= launch =================
extern "C" void kernel_launch(void* const* d_in, const int* in_sizes, int n_in,
                              void* d_out, int out_size) {
    const float* q    = (const float*)d_in[0];
    const float* k    = (const float*)d_in[1];
    const float* v    = (const float*)d_in[2];
    const int*   mask = (const int*)  d_in[3];
    const float* Wq   = (const float*)d_in[4];
    const float* Wk   = (const float*)d_in[5];
    const float* Wv   = (const float*)d_in[6];
    const float* Wo   = (const float*)d_in[7];
    float* outp  = (float*)d_out;
    float* attnp = outp + (size_t)Bn * Sn * Dn;   // outputs first, attn second

    (void)in_sizes; (void)n_in; (void)out_size;

    cudaFuncSetAttribute(attn_kernel, cudaFuncAttributeMaxDynamicSharedMemorySize, 143872);

    pack_mask_kernel<<<(Bn * Sn * Sn) / 256, 256>>>(mask);
    proj_kernel<<<dim3(4, 128, 3), 256>>>(q, k, v, Wq, Wk, Wv);
    attn_kernel<<<dim3(16, 4, 8), 512, 143872>>>(attnp);
    rescale_kernel<<<Bn * Hn * Sn, 256>>>(attnp);
    final_kernel<<<(Bn * Sn) / 16, 256>>>(Wo, outp);
}